// round 12
// baseline (speedup 1.0000x reference)
#include <cuda_runtime.h>
#include <cuda_bf16.h>
#include <cstdint>
#include <cstddef>

#define DINLINE __device__ __forceinline__

// ---------------------------------------------------------------------------
// Problem constants (fixed shapes for this dataset)
// ---------------------------------------------------------------------------
constexpr int BATCH = 2048;
constexpr int INF   = 4096;       // in_features
constexpr int OUTF  = 4096;       // out_features
constexpr int BLK   = 32;
constexpr int NCB   = INF / BLK;  // 128 col blocks
constexpr int NRB   = OUTF / BLK; // 128 row blocks
constexpr int BM    = 128;        // batch tile (MMA M per CTA)
constexpr int NBT   = BATCH / BM; // 16 batch tiles
constexpr int MAXNNZ = 4096;

// ---------------------------------------------------------------------------
// Device-global scratch (static: no cudaMalloc anywhere)
// ---------------------------------------------------------------------------
// x packed per (batch row, col-block): 64 bf16 = [hi[0..31] | lo[0..31]] = 128B
__device__ __nv_bfloat16 g_xpack[(size_t)BATCH * NCB * 64];   // ~33.5 MB
// w packed per (nnz, out-row i): 64 bf16 = [hi[0..31] | lo[0..31]] = 128B
__device__ __nv_bfloat16 g_wpack[(size_t)MAXNNZ * 32 * 64];   // ~16.8 MB
__device__ int g_off[NRB + 1];
__device__ int g_perm[MAXNNZ];

// ---------------------------------------------------------------------------
// PTX helpers — ONLY non-arch-specific instructions (target is plain sm_103:
// no tcgen05/TMEM/cta_group allowed; cp.async/ldmatrix/mma.sync are fine).
// ---------------------------------------------------------------------------
DINLINE uint32_t smem_u32(const void* p) {
    return (uint32_t)__cvta_generic_to_shared(p);
}

#define SMEM_SWIZZLE_128B(off) ((off) ^ (((off) >> 3) & 0x70))

DINLINE void cp_async16(uint32_t dst_smem, const void* src_gmem) {
    asm volatile("cp.async.cg.shared.global [%0], [%1], 16;"
                 :: "r"(dst_smem), "l"(src_gmem));
}
DINLINE void cp_async_commit() {
    asm volatile("cp.async.commit_group;\n" ::: "memory");
}
template <int N>
DINLINE void cp_async_wait() {
    asm volatile("cp.async.wait_group %0;\n" :: "n"(N) : "memory");
}

DINLINE void ldmatrix_x4(uint32_t& r0, uint32_t& r1, uint32_t& r2, uint32_t& r3,
                         uint32_t addr) {
    asm volatile("ldmatrix.sync.aligned.m8n8.x4.shared.b16 {%0,%1,%2,%3}, [%4];"
                 : "=r"(r0), "=r"(r1), "=r"(r2), "=r"(r3) : "r"(addr));
}

// D += A * B, m16n8k16, A row-major bf16, B col-major bf16, f32 accum
DINLINE void mma_16816(float* d, uint32_t a0, uint32_t a1, uint32_t a2, uint32_t a3,
                       uint32_t b0, uint32_t b1) {
    asm volatile(
        "mma.sync.aligned.m16n8k16.row.col.f32.bf16.bf16.f32 "
        "{%0,%1,%2,%3}, {%4,%5,%6,%7}, {%8,%9}, {%0,%1,%2,%3};"
        : "+f"(d[0]), "+f"(d[1]), "+f"(d[2]), "+f"(d[3])
        : "r"(a0), "r"(a1), "r"(a2), "r"(a3), "r"(b0), "r"(b1));
}

// ---------------------------------------------------------------------------
// Kernel 1: convert x (fp32) -> packed bf16 hi/lo tiles
// layout: g_xpack[(b*NCB + cb)*64 + j] = hi_j, [.. + 32 + j] = lo_j
// ---------------------------------------------------------------------------
__global__ void convert_x_kernel(const float* __restrict__ x) {
    size_t gid = (size_t)blockIdx.x * blockDim.x + threadIdx.x;
    size_t total = (size_t)BATCH * INF / 4;
    if (gid >= total) return;
    size_t b  = gid / (INF / 4);
    int    k0 = (int)(gid % (INF / 4)) * 4;
    float4 v = reinterpret_cast<const float4*>(x)[gid];
    float vv[4] = {v.x, v.y, v.z, v.w};
    __nv_bfloat16 hi[4], lo[4];
#pragma unroll
    for (int i = 0; i < 4; i++) {
        hi[i] = __float2bfloat16(vv[i]);
        lo[i] = __float2bfloat16(vv[i] - __bfloat162float(hi[i]));
    }
    int cb = k0 >> 5, j = k0 & 31;
    __nv_bfloat16* dst = g_xpack + ((size_t)b * NCB + cb) * 64;
    reinterpret_cast<__nv_bfloat162*>(dst + j)[0]      = __nv_bfloat162{hi[0], hi[1]};
    reinterpret_cast<__nv_bfloat162*>(dst + j)[1]      = __nv_bfloat162{hi[2], hi[3]};
    reinterpret_cast<__nv_bfloat162*>(dst + 32 + j)[0] = __nv_bfloat162{lo[0], lo[1]};
    reinterpret_cast<__nv_bfloat162*>(dst + 32 + j)[1] = __nv_bfloat162{lo[2], lo[3]};
}

// ---------------------------------------------------------------------------
// Kernel 2: convert w (fp32 [nnz,32,32]) -> packed bf16 hi/lo
// layout: g_wpack[(n*32 + i)*64 + j] = hi, [.. + 32 + j] = lo
// ---------------------------------------------------------------------------
__global__ void convert_w_kernel(const float* __restrict__ w, int nnz) {
    size_t gid = (size_t)blockIdx.x * blockDim.x + threadIdx.x;
    size_t total = (size_t)nnz * 1024 / 4;
    if (gid >= total) return;
    size_t n = gid / 256;
    int rem = (int)(gid % 256);
    int i  = rem >> 3;
    int j0 = (rem & 7) * 4;
    float4 v = reinterpret_cast<const float4*>(w)[gid];
    float vv[4] = {v.x, v.y, v.z, v.w};
    __nv_bfloat16 hi[4], lo[4];
#pragma unroll
    for (int q = 0; q < 4; q++) {
        hi[q] = __float2bfloat16(vv[q]);
        lo[q] = __float2bfloat16(vv[q] - __bfloat162float(hi[q]));
    }
    __nv_bfloat16* dst = g_wpack + ((size_t)n * 32 + i) * 64;
    reinterpret_cast<__nv_bfloat162*>(dst + j0)[0]      = __nv_bfloat162{hi[0], hi[1]};
    reinterpret_cast<__nv_bfloat162*>(dst + j0)[1]      = __nv_bfloat162{hi[2], hi[3]};
    reinterpret_cast<__nv_bfloat162*>(dst + 32 + j0)[0] = __nv_bfloat162{lo[0], lo[1]};
    reinterpret_cast<__nv_bfloat162*>(dst + 32 + j0)[1] = __nv_bfloat162{lo[2], lo[3]};
}

// ---------------------------------------------------------------------------
// Kernel 3: build CSR (bin nnz by output row-block). Single CTA.
// ---------------------------------------------------------------------------
__global__ void build_csr_kernel(const int* __restrict__ rows, int nnz) {
    __shared__ int cnt[NRB];
    __shared__ int offs[NRB + 1];
    __shared__ int cur[NRB];
    int t = threadIdx.x;
    if (t < NRB) cnt[t] = 0;
    __syncthreads();
    for (int n = t; n < nnz; n += blockDim.x) atomicAdd(&cnt[rows[n]], 1);
    __syncthreads();
    if (t == 0) {
        int s = 0;
        for (int i = 0; i < NRB; i++) { offs[i] = s; s += cnt[i]; }
        offs[NRB] = s;
    }
    __syncthreads();
    if (t < NRB) cur[t] = offs[t];
    if (t <= NRB) g_off[t] = offs[t];
    __syncthreads();
    for (int n = t; n < nnz; n += blockDim.x) {
        int p = atomicAdd(&cur[rows[n]], 1);
        g_perm[p] = n;
    }
}

// ---------------------------------------------------------------------------
// Kernel 4: main block-sparse MMA via mma.sync (HMMA fallback; tcgen05 is
// blocked by the sm_103 PTX target).
// grid = (NBT=16, NRB=128); 256 threads = 8 warps per CTA.
// CTA output: 128 (batch) x 32 (features of row block r). Warp w owns rows
// [16w, 16w+16). Double-buffered cp.async pipeline over the row's nnz list.
// Per nnz: A tile 128x(32hi|32lo) bf16, B tile 32x(32hi|32lo) bf16; 3-term
// split-bf16 accumulate in fp32 registers.
// ---------------------------------------------------------------------------
constexpr int A_BYTES = 128 * 128;  // 16 KB per stage
constexpr int B_BYTES = 32 * 128;   //  4 KB per stage

__global__ void __launch_bounds__(256)
bsmm_kernel(const int* __restrict__ cols, float* __restrict__ out) {
    __shared__ __align__(1024) unsigned char sA[2][A_BYTES]; // 32 KB
    __shared__ __align__(1024) unsigned char sB[2][B_BYTES]; //  8 KB

    const int tid = threadIdx.x;
    const int wid = tid >> 5;
    const int lid = tid & 31;
    const int bt  = blockIdx.x;   // batch tile
    const int r   = blockIdx.y;   // output row block

    const int start = g_off[r];
    const int cnt   = g_off[r + 1] - start;

    if (cnt == 0) {
        // zero-fill this CTA's 128x32 output region (d_out is poisoned)
        float4 z = make_float4(0.f, 0.f, 0.f, 0.f);
        for (int idx = tid; idx < BM * BLK / 4; idx += 256) {
            int row = idx >> 3, q = idx & 7;
            reinterpret_cast<float4*>(
                out + (size_t)(bt * BM + row) * OUTF + r * BLK)[q] = z;
        }
        return;
    }

    const uint32_t sA_u[2] = { smem_u32(sA[0]), smem_u32(sA[1]) };
    const uint32_t sB_u[2] = { smem_u32(sB[0]), smem_u32(sB[1]) };

    // --- stage loader: 4 A-chunks + 1 B-chunk of 16B per thread ---
    auto prefetch = [&](int it, int buf) {
        const int n = g_perm[start + it];
        const int c = __ldg(&cols[n]);
        const char* abase = reinterpret_cast<const char*>(g_xpack)
                          + ((size_t)(bt * BM) * NCB + c) * 128;
        // A: chunk idx = tid + q*256 ; row = idx>>3, i = idx&7
#pragma unroll
        for (int q = 0; q < 4; q++) {
            int idx = tid + q * 256;
            int row = idx >> 3, i = idx & 7;
            uint32_t off = (uint32_t)(row * 128 + i * 16);
            cp_async16(sA_u[buf] + SMEM_SWIZZLE_128B(off),
                       abase + (size_t)row * NCB * 128 + i * 16);
        }
        // B: 256 chunks, 1 per thread
        {
            const char* bsrc = reinterpret_cast<const char*>(g_wpack) + (size_t)n * 4096;
            int row = tid >> 3, i = tid & 7;
            uint32_t off = (uint32_t)(row * 128 + i * 16);
            cp_async16(sB_u[buf] + SMEM_SWIZZLE_128B(off), bsrc + off);
        }
        cp_async_commit();
    };

    float acc[4][4];  // [n-group g: cols 8g..8g+7][4 f32 frag regs]
#pragma unroll
    for (int g = 0; g < 4; g++)
#pragma unroll
        for (int q = 0; q < 4; q++) acc[g][q] = 0.f;

    // Precompute per-lane ldmatrix byte offsets (within a stage buffer).
    // A fragment (16x16): tile t = lid>>3, rowInTile = lid&7.
    const int a_row  = 16 * wid + ((lid >> 3) & 1) * 8 + (lid & 7);
    const int a_koff = (lid >> 4) * 16;  // tiles 2,3 -> k bytes +16
    // B fragment: lane lid -> n row lid, both x4 loads share base row.
    const int b_row = lid;

    prefetch(0, 0);

    for (int it = 0; it < cnt; ++it) {
        const int buf = it & 1;
        if (it + 1 < cnt) {
            prefetch(it + 1, buf ^ 1);
            cp_async_wait<1>();
        } else {
            cp_async_wait<0>();
        }
        __syncthreads();

        const uint32_t aS = sA_u[buf];
        const uint32_t bS = sB_u[buf];

#pragma unroll
        for (int kc = 0; kc < 2; kc++) {
            const int kb = kc * 32;  // byte base of this k16 chunk within a part
            // A hi (part byte 0) and A lo (part byte 64)
            uint32_t ah[4], al[4];
            ldmatrix_x4(ah[0], ah[1], ah[2], ah[3],
                aS + SMEM_SWIZZLE_128B((uint32_t)(a_row * 128 + 0  + kb + a_koff)));
            ldmatrix_x4(al[0], al[1], al[2], al[3],
                aS + SMEM_SWIZZLE_128B((uint32_t)(a_row * 128 + 64 + kb + a_koff)));
            // B hi: b0 set (k0-7) then b1 set (k8-15); same for lo
            uint32_t bh0[4], bh1[4], bl0[4], bl1[4];
            ldmatrix_x4(bh0[0], bh0[1], bh0[2], bh0[3],
                bS + SMEM_SWIZZLE_128B((uint32_t)(b_row * 128 + 0  + kb)));
            ldmatrix_x4(bh1[0], bh1[1], bh1[2], bh1[3],
                bS + SMEM_SWIZZLE_128B((uint32_t)(b_row * 128 + 0  + kb + 16)));
            ldmatrix_x4(bl0[0], bl0[1], bl0[2], bl0[3],
                bS + SMEM_SWIZZLE_128B((uint32_t)(b_row * 128 + 64 + kb)));
            ldmatrix_x4(bl1[0], bl1[1], bl1[2], bl1[3],
                bS + SMEM_SWIZZLE_128B((uint32_t)(b_row * 128 + 64 + kb + 16)));

#pragma unroll
            for (int g = 0; g < 4; g++) {
                mma_16816(acc[g], ah[0], ah[1], ah[2], ah[3], bh0[g], bh1[g]); // hi*hi
                mma_16816(acc[g], ah[0], ah[1], ah[2], ah[3], bl0[g], bl1[g]); // hi*lo
                mma_16816(acc[g], al[0], al[1], al[2], al[3], bh0[g], bh1[g]); // lo*hi
            }
        }
        __syncthreads();  // all warps done reading buf before it's refilled
    }

    // Epilogue: fragment -> gmem. Lane l holds rows (16w + l/4) and (+8),
    // cols 8g + (l%4)*2, +1 of output block r.
    const int row0 = bt * BM + 16 * wid + (lid >> 2);
    const int col0 = r * BLK + (lid & 3) * 2;
#pragma unroll
    for (int g = 0; g < 4; g++) {
        float2 v0 = make_float2(acc[g][0], acc[g][1]);
        float2 v1 = make_float2(acc[g][2], acc[g][3]);
        *reinterpret_cast<float2*>(out + (size_t)row0 * OUTF + col0 + 8 * g)       = v0;
        *reinterpret_cast<float2*>(out + (size_t)(row0 + 8) * OUTF + col0 + 8 * g) = v1;
    }
}

// ---------------------------------------------------------------------------
// kernel_launch
// inputs (metadata order): x f32 [2048,4096], w f32 [nnz,32,32],
// rows i32 [nnz], cols i32 [nnz], out_blocks i32
// ---------------------------------------------------------------------------
extern "C" void kernel_launch(void* const* d_in, const int* in_sizes, int n_in,
                              void* d_out, int out_size) {
    const float* x    = (const float*)d_in[0];
    const float* w    = (const float*)d_in[1];
    const int*   rows = (const int*)d_in[2];
    const int*   cols = (const int*)d_in[3];
    const int nnz = in_sizes[2];

    {
        size_t xq = (size_t)BATCH * INF / 4;
        convert_x_kernel<<<(unsigned)((xq + 255) / 256), 256>>>(x);
    }
    {
        size_t wq = (size_t)nnz * 1024 / 4;
        convert_w_kernel<<<(unsigned)((wq + 255) / 256), 256>>>(w, nnz);
    }
    build_csr_kernel<<<1, 256>>>(rows, nnz);

    dim3 grid(NBT, NRB);
    bsmm_kernel<<<grid, 256>>>(cols, (float*)d_out);
}

// round 13
// speedup vs baseline: 1.0810x; 1.0810x over previous
#include <cuda_runtime.h>
#include <cuda_bf16.h>
#include <cstdint>
#include <cstddef>

#define DINLINE __device__ __forceinline__

// ---------------------------------------------------------------------------
// Problem constants (fixed shapes for this dataset)
// ---------------------------------------------------------------------------
constexpr int BATCH = 2048;
constexpr int INF   = 4096;       // in_features
constexpr int OUTF  = 4096;       // out_features
constexpr int BLK   = 32;
constexpr int NCB   = INF / BLK;  // 128 col blocks
constexpr int NRB   = OUTF / BLK; // 128 row blocks
constexpr int BM    = 128;        // batch tile (MMA M per CTA)
constexpr int NBT   = BATCH / BM; // 16 batch tiles
constexpr int MAXNNZ = 4096;

// ---------------------------------------------------------------------------
// Device-global scratch (static: no cudaMalloc anywhere)
// ---------------------------------------------------------------------------
// x packed per (batch row, col-block): 64 bf16 = [hi[0..31] | lo[0..31]] = 128B
__device__ __nv_bfloat16 g_xpack[(size_t)BATCH * NCB * 64];   // ~33.5 MB
// w packed per (nnz, out-row i): 64 bf16 = [hi[0..31] | lo[0..31]] = 128B
__device__ __nv_bfloat16 g_wpack[(size_t)MAXNNZ * 32 * 64];   // ~16.8 MB
__device__ int g_off[NRB + 1];
__device__ int g_perm[MAXNNZ];
__device__ int g_rowmap[NRB];     // row blocks sorted by cnt desc (longest first)

// ---------------------------------------------------------------------------
// PTX helpers — ONLY non-arch-specific instructions (target is plain sm_103:
// no tcgen05/TMEM/cta_group allowed; cp.async/ldmatrix/mma.sync are fine).
// ---------------------------------------------------------------------------
DINLINE uint32_t smem_u32(const void* p) {
    return (uint32_t)__cvta_generic_to_shared(p);
}

#define SMEM_SWIZZLE_128B(off) ((off) ^ (((off) >> 3) & 0x70))

DINLINE void cp_async16(uint32_t dst_smem, const void* src_gmem) {
    asm volatile("cp.async.cg.shared.global [%0], [%1], 16;"
                 :: "r"(dst_smem), "l"(src_gmem));
}
DINLINE void cp_async_commit() {
    asm volatile("cp.async.commit_group;\n" ::: "memory");
}
template <int N>
DINLINE void cp_async_wait() {
    asm volatile("cp.async.wait_group %0;\n" :: "n"(N) : "memory");
}

DINLINE void ldmatrix_x4(uint32_t& r0, uint32_t& r1, uint32_t& r2, uint32_t& r3,
                         uint32_t addr) {
    asm volatile("ldmatrix.sync.aligned.m8n8.x4.shared.b16 {%0,%1,%2,%3}, [%4];"
                 : "=r"(r0), "=r"(r1), "=r"(r2), "=r"(r3) : "r"(addr));
}

// D += A * B, m16n8k16, A row-major bf16, B col-major bf16, f32 accum
DINLINE void mma_16816(float* d, uint32_t a0, uint32_t a1, uint32_t a2, uint32_t a3,
                       uint32_t b0, uint32_t b1) {
    asm volatile(
        "mma.sync.aligned.m16n8k16.row.col.f32.bf16.bf16.f32 "
        "{%0,%1,%2,%3}, {%4,%5,%6,%7}, {%8,%9}, {%0,%1,%2,%3};"
        : "+f"(d[0]), "+f"(d[1]), "+f"(d[2]), "+f"(d[3])
        : "r"(a0), "r"(a1), "r"(a2), "r"(a3), "r"(b0), "r"(b1));
}

// ---------------------------------------------------------------------------
// Kernel 1: convert x (fp32) -> packed bf16 hi/lo tiles
// layout: g_xpack[(b*NCB + cb)*64 + j] = hi_j, [.. + 32 + j] = lo_j
// ---------------------------------------------------------------------------
__global__ void convert_x_kernel(const float* __restrict__ x) {
    size_t gid = (size_t)blockIdx.x * blockDim.x + threadIdx.x;
    size_t total = (size_t)BATCH * INF / 4;
    if (gid >= total) return;
    size_t b  = gid / (INF / 4);
    int    k0 = (int)(gid % (INF / 4)) * 4;
    float4 v = reinterpret_cast<const float4*>(x)[gid];
    float vv[4] = {v.x, v.y, v.z, v.w};
    __nv_bfloat16 hi[4], lo[4];
#pragma unroll
    for (int i = 0; i < 4; i++) {
        hi[i] = __float2bfloat16(vv[i]);
        lo[i] = __float2bfloat16(vv[i] - __bfloat162float(hi[i]));
    }
    int cb = k0 >> 5, j = k0 & 31;
    __nv_bfloat16* dst = g_xpack + ((size_t)b * NCB + cb) * 64;
    reinterpret_cast<__nv_bfloat162*>(dst + j)[0]      = __nv_bfloat162{hi[0], hi[1]};
    reinterpret_cast<__nv_bfloat162*>(dst + j)[1]      = __nv_bfloat162{hi[2], hi[3]};
    reinterpret_cast<__nv_bfloat162*>(dst + 32 + j)[0] = __nv_bfloat162{lo[0], lo[1]};
    reinterpret_cast<__nv_bfloat162*>(dst + 32 + j)[1] = __nv_bfloat162{lo[2], lo[3]};
}

// ---------------------------------------------------------------------------
// Kernel 2: convert w (fp32 [nnz,32,32]) -> packed bf16 hi/lo
// layout: g_wpack[(n*32 + i)*64 + j] = hi, [.. + 32 + j] = lo
// ---------------------------------------------------------------------------
__global__ void convert_w_kernel(const float* __restrict__ w, int nnz) {
    size_t gid = (size_t)blockIdx.x * blockDim.x + threadIdx.x;
    size_t total = (size_t)nnz * 1024 / 4;
    if (gid >= total) return;
    size_t n = gid / 256;
    int rem = (int)(gid % 256);
    int i  = rem >> 3;
    int j0 = (rem & 7) * 4;
    float4 v = reinterpret_cast<const float4*>(w)[gid];
    float vv[4] = {v.x, v.y, v.z, v.w};
    __nv_bfloat16 hi[4], lo[4];
#pragma unroll
    for (int q = 0; q < 4; q++) {
        hi[q] = __float2bfloat16(vv[q]);
        lo[q] = __float2bfloat16(vv[q] - __bfloat162float(hi[q]));
    }
    __nv_bfloat16* dst = g_wpack + ((size_t)n * 32 + i) * 64;
    reinterpret_cast<__nv_bfloat162*>(dst + j0)[0]      = __nv_bfloat162{hi[0], hi[1]};
    reinterpret_cast<__nv_bfloat162*>(dst + j0)[1]      = __nv_bfloat162{hi[2], hi[3]};
    reinterpret_cast<__nv_bfloat162*>(dst + 32 + j0)[0] = __nv_bfloat162{lo[0], lo[1]};
    reinterpret_cast<__nv_bfloat162*>(dst + 32 + j0)[1] = __nv_bfloat162{lo[2], lo[3]};
}

// ---------------------------------------------------------------------------
// Kernel 3: build CSR (bin nnz by output row-block) + rank-sort rows by cnt
// (longest-first scheduling). Single CTA.
// ---------------------------------------------------------------------------
__global__ void build_csr_kernel(const int* __restrict__ rows, int nnz) {
    __shared__ int cnt[NRB];
    __shared__ int offs[NRB + 1];
    __shared__ int cur[NRB];
    int t = threadIdx.x;
    if (t < NRB) cnt[t] = 0;
    __syncthreads();
    for (int n = t; n < nnz; n += blockDim.x) atomicAdd(&cnt[rows[n]], 1);
    __syncthreads();
    if (t == 0) {
        int s = 0;
        for (int i = 0; i < NRB; i++) { offs[i] = s; s += cnt[i]; }
        offs[NRB] = s;
    }
    // Longest-first rank: row t goes to launch slot rank(t). Ties by index ->
    // ranks form a permutation of [0, NRB).
    if (t < NRB) {
        int c = cnt[t];
        int rank = 0;
        for (int j = 0; j < NRB; j++) {
            int cj = cnt[j];
            rank += (cj > c) || (cj == c && j < t);
        }
        g_rowmap[rank] = t;
    }
    __syncthreads();
    if (t < NRB) cur[t] = offs[t];
    if (t <= NRB) g_off[t] = offs[t];
    __syncthreads();
    for (int n = t; n < nnz; n += blockDim.x) {
        int p = atomicAdd(&cur[rows[n]], 1);
        g_perm[p] = n;
    }
}

// ---------------------------------------------------------------------------
// Kernel 4: main block-sparse MMA via mma.sync (HMMA fallback; tcgen05 is
// blocked by the sm_103 PTX target).
// grid = (NBT=16, NRB=128); 256 threads = 8 warps per CTA.
// CTA output: 128 (batch) x 32 (features of row block r = rowmap[by]).
// Double-buffered cp.async pipeline, ONE barrier per iteration:
//   wait<0> -> __syncthreads -> prefetch(it+1) -> compute(it)
// The barrier both publishes stage `it` data CTA-wide and guarantees all
// warps finished reading stage `it^1` (they read it in compute(it-1), which
// precedes this barrier) before prefetch overwrites it.
// ---------------------------------------------------------------------------
constexpr int A_BYTES = 128 * 128;  // 16 KB per stage
constexpr int B_BYTES = 32 * 128;   //  4 KB per stage

__global__ void __launch_bounds__(256)
bsmm_kernel(const int* __restrict__ cols, float* __restrict__ out) {
    __shared__ __align__(1024) unsigned char sA[2][A_BYTES]; // 32 KB
    __shared__ __align__(1024) unsigned char sB[2][B_BYTES]; //  8 KB

    const int tid = threadIdx.x;
    const int wid = tid >> 5;
    const int lid = tid & 31;
    const int bt  = blockIdx.x;            // batch tile
    const int r   = g_rowmap[blockIdx.y];  // output row block (longest first)

    const int start = g_off[r];
    const int cnt   = g_off[r + 1] - start;

    if (cnt == 0) {
        // zero-fill this CTA's 128x32 output region (d_out is poisoned)
        float4 z = make_float4(0.f, 0.f, 0.f, 0.f);
        for (int idx = tid; idx < BM * BLK / 4; idx += 256) {
            int row = idx >> 3, q = idx & 7;
            reinterpret_cast<float4*>(
                out + (size_t)(bt * BM + row) * OUTF + r * BLK)[q] = z;
        }
        return;
    }

    const uint32_t sA_u[2] = { smem_u32(sA[0]), smem_u32(sA[1]) };
    const uint32_t sB_u[2] = { smem_u32(sB[0]), smem_u32(sB[1]) };

    // --- stage loader: 4 A-chunks + 1 B-chunk of 16B per thread ---
    auto prefetch = [&](int it, int buf) {
        const int n = g_perm[start + it];
        const int c = __ldg(&cols[n]);
        const char* abase = reinterpret_cast<const char*>(g_xpack)
                          + ((size_t)(bt * BM) * NCB + c) * 128;
        // A: chunk idx = tid + q*256 ; row = idx>>3, i = idx&7
#pragma unroll
        for (int q = 0; q < 4; q++) {
            int idx = tid + q * 256;
            int row = idx >> 3, i = idx & 7;
            uint32_t off = (uint32_t)(row * 128 + i * 16);
            cp_async16(sA_u[buf] + SMEM_SWIZZLE_128B(off),
                       abase + (size_t)row * NCB * 128 + i * 16);
        }
        // B: 256 chunks, 1 per thread
        {
            const char* bsrc = reinterpret_cast<const char*>(g_wpack) + (size_t)n * 4096;
            int row = tid >> 3, i = tid & 7;
            uint32_t off = (uint32_t)(row * 128 + i * 16);
            cp_async16(sB_u[buf] + SMEM_SWIZZLE_128B(off), bsrc + off);
        }
        cp_async_commit();
    };

    float acc[4][4];  // [n-group g: cols 8g..8g+7][4 f32 frag regs]
#pragma unroll
    for (int g = 0; g < 4; g++)
#pragma unroll
        for (int q = 0; q < 4; q++) acc[g][q] = 0.f;

    // Per-lane ldmatrix row/offset parameters (loop-invariant).
    // A fragment (16x16): tile t = lid>>3, rowInTile = lid&7.
    const int a_row  = 16 * wid + ((lid >> 3) & 1) * 8 + (lid & 7);
    const int a_koff = (lid >> 4) * 16;  // tiles 2,3 -> k bytes +16
    // B fragment: lane lid -> n row lid, both x4 loads share base row.
    const int b_row = lid;

    prefetch(0, 0);

    for (int it = 0; it < cnt; ++it) {
        const int buf = it & 1;
        cp_async_wait<0>();   // stage `it` landed (only group in flight)
        __syncthreads();      // publish stage it; all warps done with it^1
        if (it + 1 < cnt) prefetch(it + 1, buf ^ 1);  // overlaps compute below

        const uint32_t aS = sA_u[buf];
        const uint32_t bS = sB_u[buf];

#pragma unroll
        for (int kc = 0; kc < 2; kc++) {
            const int kb = kc * 32;  // byte base of this k16 chunk within a part
            // A hi (part byte 0) and A lo (part byte 64)
            uint32_t ah[4], al[4];
            ldmatrix_x4(ah[0], ah[1], ah[2], ah[3],
                aS + SMEM_SWIZZLE_128B((uint32_t)(a_row * 128 + 0  + kb + a_koff)));
            ldmatrix_x4(al[0], al[1], al[2], al[3],
                aS + SMEM_SWIZZLE_128B((uint32_t)(a_row * 128 + 64 + kb + a_koff)));
            // B hi: b0 set (k0-7) then b1 set (k8-15); same for lo
            uint32_t bh0[4], bh1[4], bl0[4], bl1[4];
            ldmatrix_x4(bh0[0], bh0[1], bh0[2], bh0[3],
                bS + SMEM_SWIZZLE_128B((uint32_t)(b_row * 128 + 0  + kb)));
            ldmatrix_x4(bh1[0], bh1[1], bh1[2], bh1[3],
                bS + SMEM_SWIZZLE_128B((uint32_t)(b_row * 128 + 0  + kb + 16)));
            ldmatrix_x4(bl0[0], bl0[1], bl0[2], bl0[3],
                bS + SMEM_SWIZZLE_128B((uint32_t)(b_row * 128 + 64 + kb)));
            ldmatrix_x4(bl1[0], bl1[1], bl1[2], bl1[3],
                bS + SMEM_SWIZZLE_128B((uint32_t)(b_row * 128 + 64 + kb + 16)));

#pragma unroll
            for (int g = 0; g < 4; g++) {
                mma_16816(acc[g], ah[0], ah[1], ah[2], ah[3], bh0[g], bh1[g]); // hi*hi
                mma_16816(acc[g], ah[0], ah[1], ah[2], ah[3], bl0[g], bl1[g]); // hi*lo
                mma_16816(acc[g], al[0], al[1], al[2], al[3], bh0[g], bh1[g]); // lo*hi
            }
        }
        // no trailing barrier: next iteration's barrier (after its wait)
        // provides the read/write ordering for buffer reuse.
    }

    // Epilogue: fragment -> gmem. Lane l holds rows (16w + l/4) and (+8),
    // cols 8g + (l%4)*2, +1 of output block r.
    const int row0 = bt * BM + 16 * wid + (lid >> 2);
    const int col0 = r * BLK + (lid & 3) * 2;
#pragma unroll
    for (int g = 0; g < 4; g++) {
        float2 v0 = make_float2(acc[g][0], acc[g][1]);
        float2 v1 = make_float2(acc[g][2], acc[g][3]);
        *reinterpret_cast<float2*>(out + (size_t)row0 * OUTF + col0 + 8 * g)       = v0;
        *reinterpret_cast<float2*>(out + (size_t)(row0 + 8) * OUTF + col0 + 8 * g) = v1;
    }
}

// ---------------------------------------------------------------------------
// kernel_launch
// inputs (metadata order): x f32 [2048,4096], w f32 [nnz,32,32],
// rows i32 [nnz], cols i32 [nnz], out_blocks i32
// ---------------------------------------------------------------------------
extern "C" void kernel_launch(void* const* d_in, const int* in_sizes, int n_in,
                              void* d_out, int out_size) {
    const float* x    = (const float*)d_in[0];
    const float* w    = (const float*)d_in[1];
    const int*   rows = (const int*)d_in[2];
    const int*   cols = (const int*)d_in[3];
    const int nnz = in_sizes[2];

    {
        size_t xq = (size_t)BATCH * INF / 4;
        convert_x_kernel<<<(unsigned)((xq + 255) / 256), 256>>>(x);
    }
    {
        size_t wq = (size_t)nnz * 1024 / 4;
        convert_w_kernel<<<(unsigned)((wq + 255) / 256), 256>>>(w, nnz);
    }
    build_csr_kernel<<<1, 256>>>(rows, nnz);

    dim3 grid(NBT, NRB);
    bsmm_kernel<<<grid, 256>>>(cols, (float*)d_out);
}